// round 1
// baseline (speedup 1.0000x reference)
#include <cuda_runtime.h>

// Problem constants
#define B_   1024
#define N_   256
#define C_   128
#define H_   4
#define DH   32
#define T_   4
#define INTV 64
#define KN   192   // keys per slice = N - INTV

// Scratch (device globals; no dynamic allocation allowed)
__device__ float g_q[(size_t)B_*H_*N_*DH];       // [b][h][n][d]
__device__ float g_k[(size_t)B_*H_*N_*DH];
__device__ float g_v[(size_t)B_*H_*N_*DH];
__device__ float g_att[(size_t)B_*N_*C_];        // attention output, [b*n][c]
__device__ float g_bias[T_*H_*INTV*KN];          // [i][h][q][kk]

// ---------------------------------------------------------------------------
// Bias precompute: g_bias[i][h][q][kk] = rpb[rel[(i*64+q)*256 + other(kk)]*H + h]
// ---------------------------------------------------------------------------
__global__ void bias_kernel(const float* __restrict__ rpb,
                            const int* __restrict__ rel) {
    int idx = blockIdx.x * 256 + threadIdx.x;
    if (idx >= T_*H_*INTV*KN) return;
    int kk = idx % KN;
    int q  = (idx / KN) % INTV;
    int h  = (idx / (KN*INTV)) % H_;
    int i  =  idx / (KN*INTV*H_);
    int qg = i*INTV + q;
    int kg = (kk < i*INTV) ? kk : kk + INTV;
    g_bias[idx] = rpb[rel[qg*N_ + kg]*H_ + h];
}

// ---------------------------------------------------------------------------
// Fused QKV GEMM: [262144 x 128] @ [128 x 384] (q_w | kv_w), epilogue scatters
// into g_q/g_k/g_v with [b][h][n][d] layout.
// Block: 64(M) x 64(N) tile, full K=128 in smem, 256 threads, 4x4 per thread.
// ---------------------------------------------------------------------------
#define AS_LD 132   // 64 rows x 132 (pad for conflict-free column reads)

__global__ __launch_bounds__(256) void qkv_gemm(const float* __restrict__ x,
                                                const float* __restrict__ q_w,
                                                const float* __restrict__ kv_w) {
    extern __shared__ float sm[];
    float (*As)[AS_LD] = (float(*)[AS_LD])sm;
    float (*Bs)[64]    = (float(*)[64])(sm + 64*AS_LD);

    int tid   = threadIdx.x;
    int mBase = blockIdx.x * 64;
    int nBase = blockIdx.y * 64;

    const float* Bp; int bld, bcol;
    if (nBase < 128) { Bp = q_w;  bld = 128; bcol = nBase; }
    else             { Bp = kv_w; bld = 256; bcol = nBase - 128; }

#pragma unroll
    for (int it = 0; it < 8; ++it) {
        int idx = tid + it*256;
        int ml = idx >> 5, k4 = idx & 31;
        float4 v = *(const float4*)(x + (size_t)(mBase + ml)*128 + k4*4);
        *(float4*)&As[ml][k4*4] = v;
    }
#pragma unroll
    for (int it = 0; it < 8; ++it) {
        int idx = tid + it*256;
        int kk = idx >> 4, n4 = idx & 15;
        float4 v = *(const float4*)(Bp + (size_t)kk*bld + bcol + n4*4);
        *(float4*)&Bs[kk][n4*4] = v;
    }
    __syncthreads();

    int ty = tid >> 4, tx = tid & 15;
    int m0 = ty*4,     n0 = tx*4;
    float acc[4][4] = {};

#pragma unroll 8
    for (int k = 0; k < 128; ++k) {
        float a0 = As[m0+0][k], a1 = As[m0+1][k];
        float a2 = As[m0+2][k], a3 = As[m0+3][k];
        float4 b = *(float4*)&Bs[k][n0];
        acc[0][0] += a0*b.x; acc[0][1] += a0*b.y; acc[0][2] += a0*b.z; acc[0][3] += a0*b.w;
        acc[1][0] += a1*b.x; acc[1][1] += a1*b.y; acc[1][2] += a1*b.z; acc[1][3] += a1*b.w;
        acc[2][0] += a2*b.x; acc[2][1] += a2*b.y; acc[2][2] += a2*b.z; acc[2][3] += a2*b.w;
        acc[3][0] += a3*b.x; acc[3][1] += a3*b.y; acc[3][2] += a3*b.z; acc[3][3] += a3*b.w;
    }

    int c0 = nBase + n0;
#pragma unroll
    for (int ii = 0; ii < 4; ++ii) {
        int m = mBase + m0 + ii;
        int b = m >> 8, n = m & 255;
        float4 o = make_float4(acc[ii][0], acc[ii][1], acc[ii][2], acc[ii][3]);
        if (c0 < 128) {
            int h = c0 >> 5, d = c0 & 31;
            *(float4*)&g_q[(((size_t)b*H_ + h)*N_ + n)*DH + d] = o;
        } else if (c0 < 256) {
            int cc = c0 - 128; int h = cc >> 5, d = cc & 31;
            *(float4*)&g_k[(((size_t)b*H_ + h)*N_ + n)*DH + d] = o;
        } else {
            int cc = c0 - 256; int h = cc >> 5, d = cc & 31;
            *(float4*)&g_v[(((size_t)b*H_ + h)*N_ + n)*DH + d] = o;
        }
    }
}

// ---------------------------------------------------------------------------
// Projection GEMM: g_att [262144 x 128] @ proj_w [128 x 128] + proj_b -> d_out
// ---------------------------------------------------------------------------
__global__ __launch_bounds__(256) void proj_gemm(const float* __restrict__ pw,
                                                 const float* __restrict__ pb,
                                                 float* __restrict__ out) {
    extern __shared__ float sm[];
    float (*As)[AS_LD] = (float(*)[AS_LD])sm;
    float (*Bs)[64]    = (float(*)[64])(sm + 64*AS_LD);

    int tid   = threadIdx.x;
    int mBase = blockIdx.x * 64;
    int nBase = blockIdx.y * 64;

#pragma unroll
    for (int it = 0; it < 8; ++it) {
        int idx = tid + it*256;
        int ml = idx >> 5, k4 = idx & 31;
        float4 v = *(const float4*)(g_att + (size_t)(mBase + ml)*128 + k4*4);
        *(float4*)&As[ml][k4*4] = v;
    }
#pragma unroll
    for (int it = 0; it < 8; ++it) {
        int idx = tid + it*256;
        int kk = idx >> 4, n4 = idx & 15;
        float4 v = *(const float4*)(pw + (size_t)kk*128 + nBase + n4*4);
        *(float4*)&Bs[kk][n4*4] = v;
    }
    __syncthreads();

    int ty = tid >> 4, tx = tid & 15;
    int m0 = ty*4,     n0 = tx*4;
    float acc[4][4] = {};

#pragma unroll 8
    for (int k = 0; k < 128; ++k) {
        float a0 = As[m0+0][k], a1 = As[m0+1][k];
        float a2 = As[m0+2][k], a3 = As[m0+3][k];
        float4 b = *(float4*)&Bs[k][n0];
        acc[0][0] += a0*b.x; acc[0][1] += a0*b.y; acc[0][2] += a0*b.z; acc[0][3] += a0*b.w;
        acc[1][0] += a1*b.x; acc[1][1] += a1*b.y; acc[1][2] += a1*b.z; acc[1][3] += a1*b.w;
        acc[2][0] += a2*b.x; acc[2][1] += a2*b.y; acc[2][2] += a2*b.z; acc[2][3] += a2*b.w;
        acc[3][0] += a3*b.x; acc[3][1] += a3*b.y; acc[3][2] += a3*b.z; acc[3][3] += a3*b.w;
    }

    int c0 = nBase + n0;
    float4 bias = *(const float4*)(pb + c0);
#pragma unroll
    for (int ii = 0; ii < 4; ++ii) {
        int m = mBase + m0 + ii;
        float4 o = make_float4(acc[ii][0] + bias.x, acc[ii][1] + bias.y,
                               acc[ii][2] + bias.z, acc[ii][3] + bias.w);
        *(float4*)&out[(size_t)m*C_ + c0] = o;
    }
}

// ---------------------------------------------------------------------------
// Attention: one block per (b, i, h). 512 threads: 8 threads per query row,
// 24 keys each (interleaved kk = oct + 8j for conflict-free smem access).
// Logits + softmax fully in registers; fused PV accumulation; shfl reductions.
// ---------------------------------------------------------------------------
#define KS_LD 36   // padded row stride for Q/K/V smem tiles

__global__ __launch_bounds__(512) void attn_kernel() {
    extern __shared__ float sm[];
    float (*Qs)[KS_LD] = (float(*)[KS_LD])sm;
    float (*Ks)[KS_LD] = (float(*)[KS_LD])(sm + 64*KS_LD);
    float (*Vs)[KS_LD] = (float(*)[KS_LD])(sm + 64*KS_LD + 192*KS_LD);

    int tid = threadIdx.x;
    int bid = blockIdx.x;
    int h = bid & 3, i = (bid >> 2) & 3, b = bid >> 4;
    size_t base = ((size_t)b*H_ + h) * N_ * DH;

    {   // Q: 64 x 32 (exactly 512 float4 loads)
        int r = tid >> 3, c4 = tid & 7;
        *(float4*)&Qs[r][c4*4] =
            *(const float4*)(g_q + base + (size_t)(i*INTV + r)*DH + c4*4);
    }
#pragma unroll
    for (int it = 0; it < 3; ++it) {  // K, V: 192 x 32 each
        int idx = tid + it*512;
        int r = idx >> 3, c4 = idx & 7;
        int rg = (r < i*INTV) ? r : r + INTV;
        *(float4*)&Ks[r][c4*4] = *(const float4*)(g_k + base + (size_t)rg*DH + c4*4);
        *(float4*)&Vs[r][c4*4] = *(const float4*)(g_v + base + (size_t)rg*DH + c4*4);
    }
    __syncthreads();

    int r = tid >> 3, oct = tid & 7;

    float qr[32];
#pragma unroll
    for (int c4 = 0; c4 < 8; ++c4) {
        float4 v = *(float4*)&Qs[r][c4*4];
        qr[c4*4+0] = v.x; qr[c4*4+1] = v.y; qr[c4*4+2] = v.z; qr[c4*4+3] = v.w;
    }

    const float* brow = g_bias + ((size_t)((i*H_ + h)*INTV + r))*KN;
    float bv[24];
#pragma unroll
    for (int j = 0; j < 24; ++j) bv[j] = brow[oct + j*8];

    const float scale = 0.17677669529663687f;  // 32^-0.5
    float s[24];
    float mx = -1e30f;
#pragma unroll
    for (int j = 0; j < 24; ++j) {
        int kk = oct + j*8;
        float dot = 0.f;
#pragma unroll
        for (int c = 0; c < 32; ++c) dot += qr[c] * Ks[kk][c];
        float val = dot*scale + bv[j];
        s[j] = val;
        mx = fmaxf(mx, val);
    }
    mx = fmaxf(mx, __shfl_xor_sync(0xffffffffu, mx, 1));
    mx = fmaxf(mx, __shfl_xor_sync(0xffffffffu, mx, 2));
    mx = fmaxf(mx, __shfl_xor_sync(0xffffffffu, mx, 4));

    float acc[32];
#pragma unroll
    for (int c = 0; c < 32; ++c) acc[c] = 0.f;
    float sum = 0.f;
#pragma unroll
    for (int j = 0; j < 24; ++j) {
        int kk = oct + j*8;
        float e = __expf(s[j] - mx);
        sum += e;
#pragma unroll
        for (int c = 0; c < 32; ++c) acc[c] += e * Vs[kk][c];
    }
#pragma unroll
    for (int st = 1; st < 8; st <<= 1) {
        sum += __shfl_xor_sync(0xffffffffu, sum, st);
#pragma unroll
        for (int c = 0; c < 32; ++c)
            acc[c] += __shfl_xor_sync(0xffffffffu, acc[c], st);
    }
    float inv = 1.f / sum;

    int d0 = oct*4;
    int nq = i*INTV + r;
    float4 o = make_float4(acc[d0+0]*inv, acc[d0+1]*inv, acc[d0+2]*inv, acc[d0+3]*inv);
    *(float4*)&g_att[((size_t)b*N_ + nq)*C_ + h*DH + d0] = o;
}

// ---------------------------------------------------------------------------
// Launch
// ---------------------------------------------------------------------------
extern "C" void kernel_launch(void* const* d_in, const int* in_sizes, int n_in,
                              void* d_out, int out_size) {
    const float* x      = (const float*)d_in[0];
    const float* q_w    = (const float*)d_in[1];
    const float* kv_w   = (const float*)d_in[2];
    const float* proj_w = (const float*)d_in[3];
    const float* proj_b = (const float*)d_in[4];
    const float* rpb    = (const float*)d_in[5];
    const int*   rel    = (const int*)d_in[6];
    float* out = (float*)d_out;

    const int gemm_smem = (64*AS_LD + 128*64) * sizeof(float);   // ~66.5 KB
    const int attn_smem = (64*KS_LD + 2*192*KS_LD) * sizeof(float); // ~64.5 KB
    cudaFuncSetAttribute(qkv_gemm,  cudaFuncAttributeMaxDynamicSharedMemorySize, gemm_smem);
    cudaFuncSetAttribute(proj_gemm, cudaFuncAttributeMaxDynamicSharedMemorySize, gemm_smem);
    cudaFuncSetAttribute(attn_kernel, cudaFuncAttributeMaxDynamicSharedMemorySize, attn_smem);

    bias_kernel<<<(T_*H_*INTV*KN + 255)/256, 256>>>(rpb, rel);
    qkv_gemm<<<dim3((B_*N_)/64, 384/64), 256, gemm_smem>>>(x, q_w, kv_w);
    attn_kernel<<<B_*T_*H_, 512, attn_smem>>>();
    proj_gemm<<<dim3((B_*N_)/64, 128/64), 256, gemm_smem>>>(proj_w, proj_b, out);
}

// round 2
// speedup vs baseline: 3.0582x; 3.0582x over previous
#include <cuda_runtime.h>
#include <cstdint>

// Problem constants
#define B_   1024
#define N_   256
#define C_   128
#define H_   4
#define DH   32
#define T_   4
#define INTV 64
#define KN   192   // keys per slice = N - INTV

// Scratch (device globals; no dynamic allocation allowed)
__device__ float g_q[(size_t)B_*H_*N_*DH];       // [b][h][n][d]
__device__ float g_k[(size_t)B_*H_*N_*DH];
__device__ float g_v[(size_t)B_*H_*N_*DH];
__device__ float g_att[(size_t)B_*N_*C_];        // attention output, [b*n][c]
__device__ float g_bias[T_*H_*INTV*KN];          // [i][h][q][kk]

// ---------------------------------------------------------------------------
// helpers
// ---------------------------------------------------------------------------
__device__ __forceinline__ uint32_t f2tf(float f) {
    uint32_t u;
    asm("cvt.rna.tf32.f32 %0, %1;" : "=r"(u) : "f"(f));
    return u;
}

__device__ __forceinline__ void mma_tf32(float4& d,
                                         uint32_t a0, uint32_t a1, uint32_t a2, uint32_t a3,
                                         uint32_t b0, uint32_t b1) {
    asm volatile(
        "mma.sync.aligned.m16n8k8.row.col.f32.tf32.tf32.f32 "
        "{%0,%1,%2,%3}, {%4,%5,%6,%7}, {%8,%9}, {%0,%1,%2,%3};"
        : "+f"(d.x), "+f"(d.y), "+f"(d.z), "+f"(d.w)
        : "r"(a0), "r"(a1), "r"(a2), "r"(a3), "r"(b0), "r"(b1));
}

// ---------------------------------------------------------------------------
// Bias precompute: g_bias[i][h][q][kk] = rpb[rel[(i*64+q)*256 + other(kk)]*H + h]
// ---------------------------------------------------------------------------
__global__ void bias_kernel(const float* __restrict__ rpb,
                            const int* __restrict__ rel) {
    int idx = blockIdx.x * 256 + threadIdx.x;
    if (idx >= T_*H_*INTV*KN) return;
    int kk = idx % KN;
    int q  = (idx / KN) % INTV;
    int h  = (idx / (KN*INTV)) % H_;
    int i  =  idx / (KN*INTV*H_);
    int qg = i*INTV + q;
    int kg = (kk < i*INTV) ? kk : kk + INTV;
    g_bias[idx] = rpb[rel[qg*N_ + kg]*H_ + h];
}

// ---------------------------------------------------------------------------
// QKV GEMM via tf32 mma: [262144 x 128] @ [128 x 384], scatter epilogue.
// Block tile 128(M) x 64(N), K=128 resident. 8 warps, warp tile 32x32.
// ---------------------------------------------------------------------------
#define AS_LD 132   // 132 % 32 == 4 -> conflict-free A-fragment loads
#define BS_LD 72    // 72 % 32 == 8  -> conflict-free B-fragment loads

__device__ __forceinline__ void store_qkv(int m, int cg, float2 v) {
    int b = m >> 8, n = m & 255;
    if (cg < 128) {
        int h = cg >> 5, d = cg & 31;
        *(float2*)&g_q[(((size_t)b*H_ + h)*N_ + n)*DH + d] = v;
    } else if (cg < 256) {
        int cc = cg - 128; int h = cc >> 5, d = cc & 31;
        *(float2*)&g_k[(((size_t)b*H_ + h)*N_ + n)*DH + d] = v;
    } else {
        int cc = cg - 256; int h = cc >> 5, d = cc & 31;
        *(float2*)&g_v[(((size_t)b*H_ + h)*N_ + n)*DH + d] = v;
    }
}

__global__ __launch_bounds__(256) void qkv_gemm_tc(const float* __restrict__ x,
                                                   const float* __restrict__ q_w,
                                                   const float* __restrict__ kv_w) {
    extern __shared__ uint32_t sm[];
    uint32_t* As = sm;                  // [128][AS_LD]
    uint32_t* Bs = sm + 128*AS_LD;      // [128][BS_LD]

    int tid   = threadIdx.x;
    int mBase = blockIdx.x * 128;
    int nBase = blockIdx.y * 64;

    const float* Bp; int bld, bcol;
    if (nBase < 128) { Bp = q_w;  bld = 128; bcol = nBase; }
    else             { Bp = kv_w; bld = 256; bcol = nBase - 128; }

#pragma unroll
    for (int it = 0; it < 16; ++it) {   // A: 128x128
        int idx = tid + it*256;
        int r = idx >> 5, c4 = idx & 31;
        float4 v = *(const float4*)(x + (size_t)(mBase + r)*128 + c4*4);
        uint32_t* p = As + r*AS_LD + c4*4;
        p[0] = f2tf(v.x); p[1] = f2tf(v.y); p[2] = f2tf(v.z); p[3] = f2tf(v.w);
    }
#pragma unroll
    for (int it = 0; it < 8; ++it) {    // B: 128x64
        int idx = tid + it*256;
        int r = idx >> 4, c4 = idx & 15;
        float4 v = *(const float4*)(Bp + (size_t)r*bld + bcol + c4*4);
        uint32_t* p = Bs + r*BS_LD + c4*4;
        p[0] = f2tf(v.x); p[1] = f2tf(v.y); p[2] = f2tf(v.z); p[3] = f2tf(v.w);
    }
    __syncthreads();

    int warp = tid >> 5, lane = tid & 31;
    int g = lane >> 2, q = lane & 3;
    int m0w = (warp & 3) * 32;
    int n0w = (warp >> 2) * 32;

    float4 c[2][4];
#pragma unroll
    for (int mi = 0; mi < 2; ++mi)
#pragma unroll
        for (int nj = 0; nj < 4; ++nj) c[mi][nj] = make_float4(0.f, 0.f, 0.f, 0.f);

#pragma unroll
    for (int k0 = 0; k0 < 128; k0 += 8) {
        uint32_t a[2][4];
#pragma unroll
        for (int mi = 0; mi < 2; ++mi) {
            int r = m0w + mi*16 + g;
            a[mi][0] = As[r*AS_LD + k0 + q];
            a[mi][1] = As[(r+8)*AS_LD + k0 + q];
            a[mi][2] = As[r*AS_LD + k0 + q + 4];
            a[mi][3] = As[(r+8)*AS_LD + k0 + q + 4];
        }
#pragma unroll
        for (int nj = 0; nj < 4; ++nj) {
            uint32_t b0 = Bs[(k0+q)*BS_LD   + n0w + nj*8 + g];
            uint32_t b1 = Bs[(k0+q+4)*BS_LD + n0w + nj*8 + g];
            mma_tf32(c[0][nj], a[0][0], a[0][1], a[0][2], a[0][3], b0, b1);
            mma_tf32(c[1][nj], a[1][0], a[1][1], a[1][2], a[1][3], b0, b1);
        }
    }

#pragma unroll
    for (int mi = 0; mi < 2; ++mi)
#pragma unroll
        for (int nj = 0; nj < 4; ++nj) {
            int r  = mBase + m0w + mi*16 + g;
            int cg = nBase + n0w + nj*8 + 2*q;
            store_qkv(r,     cg, make_float2(c[mi][nj].x, c[mi][nj].y));
            store_qkv(r + 8, cg, make_float2(c[mi][nj].z, c[mi][nj].w));
        }
}

// ---------------------------------------------------------------------------
// Projection GEMM via tf32 mma: g_att [262144 x 128] @ proj_w [128 x 128] + b
// ---------------------------------------------------------------------------
__global__ __launch_bounds__(256) void proj_gemm_tc(const float* __restrict__ pw,
                                                    const float* __restrict__ pb,
                                                    float* __restrict__ out) {
    extern __shared__ uint32_t sm[];
    uint32_t* As = sm;
    uint32_t* Bs = sm + 128*AS_LD;

    int tid   = threadIdx.x;
    int mBase = blockIdx.x * 128;
    int nBase = blockIdx.y * 64;

#pragma unroll
    for (int it = 0; it < 16; ++it) {
        int idx = tid + it*256;
        int r = idx >> 5, c4 = idx & 31;
        float4 v = *(const float4*)(g_att + (size_t)(mBase + r)*128 + c4*4);
        uint32_t* p = As + r*AS_LD + c4*4;
        p[0] = f2tf(v.x); p[1] = f2tf(v.y); p[2] = f2tf(v.z); p[3] = f2tf(v.w);
    }
#pragma unroll
    for (int it = 0; it < 8; ++it) {
        int idx = tid + it*256;
        int r = idx >> 4, c4 = idx & 15;
        float4 v = *(const float4*)(pw + (size_t)r*128 + nBase + c4*4);
        uint32_t* p = Bs + r*BS_LD + c4*4;
        p[0] = f2tf(v.x); p[1] = f2tf(v.y); p[2] = f2tf(v.z); p[3] = f2tf(v.w);
    }
    __syncthreads();

    int warp = tid >> 5, lane = tid & 31;
    int g = lane >> 2, q = lane & 3;
    int m0w = (warp & 3) * 32;
    int n0w = (warp >> 2) * 32;

    float4 c[2][4];
#pragma unroll
    for (int mi = 0; mi < 2; ++mi)
#pragma unroll
        for (int nj = 0; nj < 4; ++nj) c[mi][nj] = make_float4(0.f, 0.f, 0.f, 0.f);

#pragma unroll
    for (int k0 = 0; k0 < 128; k0 += 8) {
        uint32_t a[2][4];
#pragma unroll
        for (int mi = 0; mi < 2; ++mi) {
            int r = m0w + mi*16 + g;
            a[mi][0] = As[r*AS_LD + k0 + q];
            a[mi][1] = As[(r+8)*AS_LD + k0 + q];
            a[mi][2] = As[r*AS_LD + k0 + q + 4];
            a[mi][3] = As[(r+8)*AS_LD + k0 + q + 4];
        }
#pragma unroll
        for (int nj = 0; nj < 4; ++nj) {
            uint32_t b0 = Bs[(k0+q)*BS_LD   + n0w + nj*8 + g];
            uint32_t b1 = Bs[(k0+q+4)*BS_LD + n0w + nj*8 + g];
            mma_tf32(c[0][nj], a[0][0], a[0][1], a[0][2], a[0][3], b0, b1);
            mma_tf32(c[1][nj], a[1][0], a[1][1], a[1][2], a[1][3], b0, b1);
        }
    }

#pragma unroll
    for (int mi = 0; mi < 2; ++mi)
#pragma unroll
        for (int nj = 0; nj < 4; ++nj) {
            int r  = mBase + m0w + mi*16 + g;
            int cg = nBase + n0w + nj*8 + 2*q;
            float2 bias = *(const float2*)(pb + cg);
            float2 v0 = make_float2(c[mi][nj].x + bias.x, c[mi][nj].y + bias.y);
            float2 v1 = make_float2(c[mi][nj].z + bias.x, c[mi][nj].w + bias.y);
            *(float2*)&out[(size_t)r*C_ + cg]       = v0;
            *(float2*)&out[(size_t)(r+8)*C_ + cg]   = v1;
        }
}

// ---------------------------------------------------------------------------
// Attention via tf32 mma: one block per (b, i, h). 256 threads (8 warps).
// Warp grid 4(m) x 2(n): QK warp tile 16x96 (12 C frags in regs, bias-init),
// register softmax + quad shuffles + tiny smem cross-warp reduce, then
// C-frag -> A-frag shuffle transform feeds PV mma. Partial O reduced in smem.
// ---------------------------------------------------------------------------
#define QS_LD 36
#define KS_LDT 36
#define VS_LD 40
#define OP_LD 34

#define QS_OFF 0
#define KS_OFF (64*QS_LD)                    // 2304
#define VS_OFF (KS_OFF + 192*KS_LDT)         // 9216
#define OP_OFF (VS_OFF + 192*VS_LD)          // 16896 (floats)
#define RM_OFF (OP_OFF + 64*OP_LD)           // 19072
#define RS_OFF (RM_OFF + 128)                // 19200
#define ATTN_SMEM_WORDS (RS_OFF + 128)       // 19328

__global__ __launch_bounds__(256) void attn_tc() {
    extern __shared__ uint32_t sm[];
    uint32_t* Qs = sm + QS_OFF;
    uint32_t* Ks = sm + KS_OFF;
    uint32_t* Vs = sm + VS_OFF;
    float* opart = (float*)(sm + OP_OFF);
    float* redM  = (float*)(sm + RM_OFF);   // [2][64]
    float* redS  = (float*)(sm + RS_OFF);   // [2][64]

    int tid = threadIdx.x;
    int bid = blockIdx.x;
    int h = bid & 3, i = (bid >> 2) & 3, b = bid >> 4;
    size_t base = ((size_t)b*H_ + h) * N_ * DH;

    const float scale = 0.17677669529663687f;  // 32^-0.5

    // stage Q (scaled), K, V as tf32 bits
#pragma unroll
    for (int it = 0; it < 2; ++it) {            // Q: 64x32
        int idx = tid + it*256;
        int r = idx >> 3, c4 = idx & 7;
        float4 v = *(const float4*)(g_q + base + (size_t)(i*INTV + r)*DH + c4*4);
        uint32_t* p = Qs + r*QS_LD + c4*4;
        p[0] = f2tf(v.x*scale); p[1] = f2tf(v.y*scale);
        p[2] = f2tf(v.z*scale); p[3] = f2tf(v.w*scale);
    }
#pragma unroll
    for (int it = 0; it < 6; ++it) {            // K,V: 192x32 each
        int idx = tid + it*256;
        int r = idx >> 3, c4 = idx & 7;
        int rg = (r < i*INTV) ? r : r + INTV;
        float4 kv = *(const float4*)(g_k + base + (size_t)rg*DH + c4*4);
        float4 vv = *(const float4*)(g_v + base + (size_t)rg*DH + c4*4);
        uint32_t* pk = Ks + r*KS_LDT + c4*4;
        pk[0] = f2tf(kv.x); pk[1] = f2tf(kv.y); pk[2] = f2tf(kv.z); pk[3] = f2tf(kv.w);
        uint32_t* pv = Vs + r*VS_LD + c4*4;
        pv[0] = f2tf(vv.x); pv[1] = f2tf(vv.y); pv[2] = f2tf(vv.z); pv[3] = f2tf(vv.w);
    }
    __syncthreads();

    int warp = tid >> 5, lane = tid & 31;
    int g = lane >> 2, q = lane & 3;
    int wm = warp >> 1, wn = warp & 1;
    int m0 = wm * 16;
    int r0 = m0 + g, r1 = r0 + 8;

    // S frags initialized with bias
    float4 c[12];
    {
        const float* bb = g_bias + ((size_t)((i*H_ + h)*INTV))*KN;
#pragma unroll
        for (int kt = 0; kt < 12; ++kt) {
            int col = wn*96 + kt*8 + 2*q;
            float2 b0 = *(const float2*)(bb + (size_t)r0*KN + col);
            float2 b1 = *(const float2*)(bb + (size_t)r1*KN + col);
            c[kt] = make_float4(b0.x, b0.y, b1.x, b1.y);
        }
    }

    // S = scale*Q K^T + bias
#pragma unroll
    for (int k0 = 0; k0 < 32; k0 += 8) {
        uint32_t a0 = Qs[r0*QS_LD + k0 + q];
        uint32_t a1 = Qs[r1*QS_LD + k0 + q];
        uint32_t a2 = Qs[r0*QS_LD + k0 + q + 4];
        uint32_t a3 = Qs[r1*QS_LD + k0 + q + 4];
#pragma unroll
        for (int kt = 0; kt < 12; ++kt) {
            int n = wn*96 + kt*8 + g;
            uint32_t b0 = Ks[n*KS_LDT + k0 + q];
            uint32_t b1 = Ks[n*KS_LDT + k0 + q + 4];
            mma_tf32(c[kt], a0, a1, a2, a3, b0, b1);
        }
    }

    // row max (this warp's 96 cols)
    float mx0 = -1e30f, mx1 = -1e30f;
#pragma unroll
    for (int kt = 0; kt < 12; ++kt) {
        mx0 = fmaxf(mx0, fmaxf(c[kt].x, c[kt].y));
        mx1 = fmaxf(mx1, fmaxf(c[kt].z, c[kt].w));
    }
    mx0 = fmaxf(mx0, __shfl_xor_sync(0xffffffffu, mx0, 1));
    mx0 = fmaxf(mx0, __shfl_xor_sync(0xffffffffu, mx0, 2));
    mx1 = fmaxf(mx1, __shfl_xor_sync(0xffffffffu, mx1, 1));
    mx1 = fmaxf(mx1, __shfl_xor_sync(0xffffffffu, mx1, 2));
    if (q == 0) { redM[wn*64 + r0] = mx0; redM[wn*64 + r1] = mx1; }
    __syncthreads();
    float m0f = fmaxf(redM[r0], redM[64 + r0]);
    float m1f = fmaxf(redM[r1], redM[64 + r1]);

    // exp + row sum
    float s0 = 0.f, s1 = 0.f;
#pragma unroll
    for (int kt = 0; kt < 12; ++kt) {
        c[kt].x = __expf(c[kt].x - m0f);
        c[kt].y = __expf(c[kt].y - m0f);
        c[kt].z = __expf(c[kt].z - m1f);
        c[kt].w = __expf(c[kt].w - m1f);
        s0 += c[kt].x + c[kt].y;
        s1 += c[kt].z + c[kt].w;
    }
    s0 += __shfl_xor_sync(0xffffffffu, s0, 1);
    s0 += __shfl_xor_sync(0xffffffffu, s0, 2);
    s1 += __shfl_xor_sync(0xffffffffu, s1, 1);
    s1 += __shfl_xor_sync(0xffffffffu, s1, 2);
    if (q == 0) { redS[wn*64 + r0] = s0; redS[wn*64 + r1] = s1; }
    __syncthreads();
    float inv0 = 1.f / (redS[r0] + redS[64 + r0]);
    float inv1 = 1.f / (redS[r1] + redS[64 + r1]);

    // PV: O(16x32) partial over this warp's 96 keys
    float4 o[4];
#pragma unroll
    for (int nj = 0; nj < 4; ++nj) o[nj] = make_float4(0.f, 0.f, 0.f, 0.f);

    int srcA = (lane & ~3) | (q >> 1);
    int srcB = srcA + 2;
#pragma unroll
    for (int kt = 0; kt < 12; ++kt) {
        float cx = c[kt].x, cy = c[kt].y, cz = c[kt].z, cw = c[kt].w;
        float t0 = __shfl_sync(0xffffffffu, cx, srcA);
        float t1 = __shfl_sync(0xffffffffu, cy, srcA);
        float t2 = __shfl_sync(0xffffffffu, cz, srcA);
        float t3 = __shfl_sync(0xffffffffu, cw, srcA);
        float t4 = __shfl_sync(0xffffffffu, cx, srcB);
        float t5 = __shfl_sync(0xffffffffu, cy, srcB);
        float t6 = __shfl_sync(0xffffffffu, cz, srcB);
        float t7 = __shfl_sync(0xffffffffu, cw, srcB);
        uint32_t a0 = f2tf((q & 1) ? t1 : t0);
        uint32_t a1 = f2tf((q & 1) ? t3 : t2);
        uint32_t a2 = f2tf((q & 1) ? t5 : t4);
        uint32_t a3 = f2tf((q & 1) ? t7 : t6);
        int kbase = wn*96 + kt*8;
#pragma unroll
        for (int nj = 0; nj < 4; ++nj) {
            uint32_t b0 = Vs[(kbase + q)*VS_LD     + nj*8 + g];
            uint32_t b1 = Vs[(kbase + q + 4)*VS_LD + nj*8 + g];
            mma_tf32(o[nj], a0, a1, a2, a3, b0, b1);
        }
    }

    // cross-warp reduce (wn pairs) + normalize + writeout
    if (wn == 1) {
#pragma unroll
        for (int nj = 0; nj < 4; ++nj) {
            int cb = nj*8 + 2*q;
            opart[r0*OP_LD + cb]     = o[nj].x;
            opart[r0*OP_LD + cb + 1] = o[nj].y;
            opart[r1*OP_LD + cb]     = o[nj].z;
            opart[r1*OP_LD + cb + 1] = o[nj].w;
        }
    }
    __syncthreads();
    if (wn == 0) {
        int nq0 = i*INTV + r0, nq1 = i*INTV + r1;
#pragma unroll
        for (int nj = 0; nj < 4; ++nj) {
            int cb = nj*8 + 2*q;
            float2 v0 = make_float2((o[nj].x + opart[r0*OP_LD + cb])     * inv0,
                                    (o[nj].y + opart[r0*OP_LD + cb + 1]) * inv0);
            float2 v1 = make_float2((o[nj].z + opart[r1*OP_LD + cb])     * inv1,
                                    (o[nj].w + opart[r1*OP_LD + cb + 1]) * inv1);
            *(float2*)&g_att[((size_t)b*N_ + nq0)*C_ + h*DH + cb] = v0;
            *(float2*)&g_att[((size_t)b*N_ + nq1)*C_ + h*DH + cb] = v1;
        }
    }
}

// ---------------------------------------------------------------------------
// Launch
// ---------------------------------------------------------------------------
extern "C" void kernel_launch(void* const* d_in, const int* in_sizes, int n_in,
                              void* d_out, int out_size) {
    const float* x      = (const float*)d_in[0];
    const float* q_w    = (const float*)d_in[1];
    const float* kv_w   = (const float*)d_in[2];
    const float* proj_w = (const float*)d_in[3];
    const float* proj_b = (const float*)d_in[4];
    const float* rpb    = (const float*)d_in[5];
    const int*   rel    = (const int*)d_in[6];
    float* out = (float*)d_out;

    const int gemm_smem = (128*AS_LD + 128*BS_LD) * 4;   // 104448 B
    const int attn_smem = ATTN_SMEM_WORDS * 4;           // 77312 B
    cudaFuncSetAttribute(qkv_gemm_tc,  cudaFuncAttributeMaxDynamicSharedMemorySize, gemm_smem);
    cudaFuncSetAttribute(proj_gemm_tc, cudaFuncAttributeMaxDynamicSharedMemorySize, gemm_smem);
    cudaFuncSetAttribute(attn_tc,      cudaFuncAttributeMaxDynamicSharedMemorySize, attn_smem);

    bias_kernel<<<(T_*H_*INTV*KN + 255)/256, 256>>>(rpb, rel);
    qkv_gemm_tc<<<dim3((B_*N_)/128, 384/64), 256, gemm_smem>>>(x, q_w, kv_w);
    attn_tc<<<B_*T_*H_, 256, attn_smem>>>();
    proj_gemm_tc<<<dim3((B_*N_)/128, 128/64), 256, gemm_smem>>>(proj_w, proj_b, out);
}

// round 3
// speedup vs baseline: 3.4175x; 1.1175x over previous
#include <cuda_runtime.h>
#include <cstdint>

// Problem constants
#define B_   1024
#define N_   256
#define C_   128
#define H_   4
#define DH   32
#define T_   4
#define INTV 64
#define KN   192   // keys per slice = N - INTV

// Scratch (device globals; no dynamic allocation allowed)
__device__ float g_q[(size_t)B_*H_*N_*DH];       // [b][h][n][d]
__device__ float g_k[(size_t)B_*H_*N_*DH];
__device__ float g_v[(size_t)B_*H_*N_*DH];
__device__ float g_att[(size_t)B_*N_*C_];        // attention output, [b*n][c]
__device__ float g_bias[T_*H_*INTV*KN];          // [i][h][q][kk]

// ---------------------------------------------------------------------------
// helpers
// ---------------------------------------------------------------------------
__device__ __forceinline__ uint32_t f2tf(float f) {
    uint32_t u;
    asm("cvt.rna.tf32.f32 %0, %1;" : "=r"(u) : "f"(f));
    return u;
}

__device__ __forceinline__ void mma_tf32(float4& d,
                                         uint32_t a0, uint32_t a1, uint32_t a2, uint32_t a3,
                                         uint32_t b0, uint32_t b1) {
    asm volatile(
        "mma.sync.aligned.m16n8k8.row.col.f32.tf32.tf32.f32 "
        "{%0,%1,%2,%3}, {%4,%5,%6,%7}, {%8,%9}, {%0,%1,%2,%3};"
        : "+f"(d.x), "+f"(d.y), "+f"(d.z), "+f"(d.w)
        : "r"(a0), "r"(a1), "r"(a2), "r"(a3), "r"(b0), "r"(b1));
}

// ---------------------------------------------------------------------------
// Bias precompute
// ---------------------------------------------------------------------------
__global__ void bias_kernel(const float* __restrict__ rpb,
                            const int* __restrict__ rel) {
    int idx = blockIdx.x * 256 + threadIdx.x;
    if (idx >= T_*H_*INTV*KN) return;
    int kk = idx % KN;
    int q  = (idx / KN) % INTV;
    int h  = (idx / (KN*INTV)) % H_;
    int i  =  idx / (KN*INTV*H_);
    int qg = i*INTV + q;
    int kg = (kk < i*INTV) ? kk : kk + INTV;
    g_bias[idx] = rpb[rel[qg*N_ + kg]*H_ + h];
}

// ---------------------------------------------------------------------------
// QKV GEMM: block = 256 M-rows, A resident (read-once), 6 N-chunks of 64.
// 512 threads, 16 warps as 4(m) x 4(n): warp tile 64 x 16.
// ---------------------------------------------------------------------------
#define QA_LD 132
#define QB_LD 68

__device__ __forceinline__ void store_qkv(int m, int cg, float2 v) {
    int b = m >> 8, n = m & 255;
    if (cg < 128) {
        int h = cg >> 5, d = cg & 31;
        *(float2*)&g_q[(((size_t)b*H_ + h)*N_ + n)*DH + d] = v;
    } else if (cg < 256) {
        int cc = cg - 128; int h = cc >> 5, d = cc & 31;
        *(float2*)&g_k[(((size_t)b*H_ + h)*N_ + n)*DH + d] = v;
    } else {
        int cc = cg - 256; int h = cc >> 5, d = cc & 31;
        *(float2*)&g_v[(((size_t)b*H_ + h)*N_ + n)*DH + d] = v;
    }
}

__global__ __launch_bounds__(512) void qkv_gemm_tc(const float* __restrict__ x,
                                                   const float* __restrict__ q_w,
                                                   const float* __restrict__ kv_w) {
    extern __shared__ uint32_t sm[];
    uint32_t* As = sm;                   // [256][QA_LD]
    uint32_t* Bs = sm + 256*QA_LD;       // [128][QB_LD]

    int tid   = threadIdx.x;
    int mBase = blockIdx.x * 256;

#pragma unroll
    for (int it = 0; it < 16; ++it) {    // A: 256x128
        int idx = tid + it*512;
        int r = idx >> 5, c4 = idx & 31;
        float4 v = *(const float4*)(x + (size_t)(mBase + r)*128 + c4*4);
        uint32_t* p = As + r*QA_LD + c4*4;
        p[0] = f2tf(v.x); p[1] = f2tf(v.y); p[2] = f2tf(v.z); p[3] = f2tf(v.w);
    }

    int warp = tid >> 5, lane = tid & 31;
    int g = lane >> 2, q = lane & 3;
    int wm = (warp & 3) * 64;
    int wn = (warp >> 2) * 16;

    for (int c = 0; c < 6; ++c) {
        const float* Bp; int bld, bcol;
        if (c < 2) { Bp = q_w;  bld = 128; bcol = c*64; }
        else       { Bp = kv_w; bld = 256; bcol = (c-2)*64; }

        __syncthreads();   // prior chunk compute done before B overwrite
#pragma unroll
        for (int it = 0; it < 4; ++it) {  // B chunk: 128x64
            int idx = tid + it*512;
            int r = idx >> 4, c4 = idx & 15;
            float4 v = *(const float4*)(Bp + (size_t)r*bld + bcol + c4*4);
            uint32_t* p = Bs + r*QB_LD + c4*4;
            p[0] = f2tf(v.x); p[1] = f2tf(v.y); p[2] = f2tf(v.z); p[3] = f2tf(v.w);
        }
        __syncthreads();

        float4 acc[4][2];
#pragma unroll
        for (int mi = 0; mi < 4; ++mi)
#pragma unroll
            for (int nj = 0; nj < 2; ++nj) acc[mi][nj] = make_float4(0.f,0.f,0.f,0.f);

#pragma unroll
        for (int k0 = 0; k0 < 128; k0 += 8) {
            uint32_t a[4][4];
#pragma unroll
            for (int mi = 0; mi < 4; ++mi) {
                int r = wm + mi*16 + g;
                a[mi][0] = As[r*QA_LD + k0 + q];
                a[mi][1] = As[(r+8)*QA_LD + k0 + q];
                a[mi][2] = As[r*QA_LD + k0 + q + 4];
                a[mi][3] = As[(r+8)*QA_LD + k0 + q + 4];
            }
#pragma unroll
            for (int nj = 0; nj < 2; ++nj) {
                uint32_t b0 = Bs[(k0+q)*QB_LD   + wn + nj*8 + g];
                uint32_t b1 = Bs[(k0+q+4)*QB_LD + wn + nj*8 + g];
#pragma unroll
                for (int mi = 0; mi < 4; ++mi)
                    mma_tf32(acc[mi][nj], a[mi][0], a[mi][1], a[mi][2], a[mi][3], b0, b1);
            }
        }

#pragma unroll
        for (int mi = 0; mi < 4; ++mi)
#pragma unroll
            for (int nj = 0; nj < 2; ++nj) {
                int r  = mBase + wm + mi*16 + g;
                int cg = c*64 + wn + nj*8 + 2*q;
                store_qkv(r,     cg, make_float2(acc[mi][nj].x, acc[mi][nj].y));
                store_qkv(r + 8, cg, make_float2(acc[mi][nj].z, acc[mi][nj].w));
            }
    }
}

// ---------------------------------------------------------------------------
// Projection GEMM: block = 256 x 128 (single N pass, A read-once).
// 512 threads, 16 warps as 4(m) x 4(n): warp tile 64 x 32.
// ---------------------------------------------------------------------------
#define PB_LD 132

__global__ __launch_bounds__(512) void proj_gemm_tc(const float* __restrict__ pw,
                                                    const float* __restrict__ pb,
                                                    float* __restrict__ out) {
    extern __shared__ uint32_t sm[];
    uint32_t* As = sm;                   // [256][QA_LD]
    uint32_t* Bs = sm + 256*QA_LD;       // [128][PB_LD]

    int tid   = threadIdx.x;
    int mBase = blockIdx.x * 256;

#pragma unroll
    for (int it = 0; it < 16; ++it) {    // A: 256x128
        int idx = tid + it*512;
        int r = idx >> 5, c4 = idx & 31;
        float4 v = *(const float4*)(g_att + (size_t)(mBase + r)*128 + c4*4);
        uint32_t* p = As + r*QA_LD + c4*4;
        p[0] = f2tf(v.x); p[1] = f2tf(v.y); p[2] = f2tf(v.z); p[3] = f2tf(v.w);
    }
#pragma unroll
    for (int it = 0; it < 8; ++it) {     // B: 128x128
        int idx = tid + it*512;
        int r = idx >> 5, c4 = idx & 31;
        float4 v = *(const float4*)(pw + (size_t)r*128 + c4*4);
        uint32_t* p = Bs + r*PB_LD + c4*4;
        p[0] = f2tf(v.x); p[1] = f2tf(v.y); p[2] = f2tf(v.z); p[3] = f2tf(v.w);
    }
    __syncthreads();

    int warp = tid >> 5, lane = tid & 31;
    int g = lane >> 2, q = lane & 3;
    int wm = (warp & 3) * 64;
    int wn = (warp >> 2) * 32;

    float4 acc[4][4];
#pragma unroll
    for (int mi = 0; mi < 4; ++mi)
#pragma unroll
        for (int nj = 0; nj < 4; ++nj) acc[mi][nj] = make_float4(0.f,0.f,0.f,0.f);

#pragma unroll
    for (int k0 = 0; k0 < 128; k0 += 8) {
        uint32_t a[4][4];
#pragma unroll
        for (int mi = 0; mi < 4; ++mi) {
            int r = wm + mi*16 + g;
            a[mi][0] = As[r*QA_LD + k0 + q];
            a[mi][1] = As[(r+8)*QA_LD + k0 + q];
            a[mi][2] = As[r*QA_LD + k0 + q + 4];
            a[mi][3] = As[(r+8)*QA_LD + k0 + q + 4];
        }
#pragma unroll
        for (int nj = 0; nj < 4; ++nj) {
            uint32_t b0 = Bs[(k0+q)*PB_LD   + wn + nj*8 + g];
            uint32_t b1 = Bs[(k0+q+4)*PB_LD + wn + nj*8 + g];
#pragma unroll
            for (int mi = 0; mi < 4; ++mi)
                mma_tf32(acc[mi][nj], a[mi][0], a[mi][1], a[mi][2], a[mi][3], b0, b1);
        }
    }

#pragma unroll
    for (int nj = 0; nj < 4; ++nj) {
        int cg = wn + nj*8 + 2*q;
        float2 bias = *(const float2*)(pb + cg);
#pragma unroll
        for (int mi = 0; mi < 4; ++mi) {
            int r = mBase + wm + mi*16 + g;
            float2 v0 = make_float2(acc[mi][nj].x + bias.x, acc[mi][nj].y + bias.y);
            float2 v1 = make_float2(acc[mi][nj].z + bias.x, acc[mi][nj].w + bias.y);
            *(float2*)&out[(size_t)r*C_ + cg]     = v0;
            *(float2*)&out[(size_t)(r+8)*C_ + cg] = v1;
        }
    }
}

// ---------------------------------------------------------------------------
// Attention: block per (b, h), 512 threads (16 warps). Q/K/V (256x32 each)
// loaded once. Warp w owns query rows w*16..w*16+15 (slice i = w/4) and ALL
// 192 keys of that slice -> softmax fully in-warp; slice masking via key
// index offset. S frags bias-initialized; shuffle-transform feeds PV mma.
// ---------------------------------------------------------------------------
#define TS_LD 36

__global__ __launch_bounds__(512) void attn_tc() {
    extern __shared__ uint32_t sm[];
    uint32_t* Qs = sm;                   // [256][TS_LD]
    uint32_t* Ks = sm + 256*TS_LD;
    uint32_t* Vs = sm + 512*TS_LD;

    int tid = threadIdx.x;
    int bid = blockIdx.x;
    int h = bid & 3, b = bid >> 2;
    size_t base = ((size_t)b*H_ + h) * N_ * DH;

    const float scale = 0.17677669529663687f;  // 32^-0.5

#pragma unroll
    for (int it = 0; it < 4; ++it) {     // Q,K,V: 256x32 each
        int idx = tid + it*512;
        int r = idx >> 3, c4 = idx & 7;
        float4 qv = *(const float4*)(g_q + base + (size_t)r*DH + c4*4);
        float4 kv = *(const float4*)(g_k + base + (size_t)r*DH + c4*4);
        float4 vv = *(const float4*)(g_v + base + (size_t)r*DH + c4*4);
        uint32_t* pq = Qs + r*TS_LD + c4*4;
        pq[0] = f2tf(qv.x*scale); pq[1] = f2tf(qv.y*scale);
        pq[2] = f2tf(qv.z*scale); pq[3] = f2tf(qv.w*scale);
        uint32_t* pk = Ks + r*TS_LD + c4*4;
        pk[0] = f2tf(kv.x); pk[1] = f2tf(kv.y); pk[2] = f2tf(kv.z); pk[3] = f2tf(kv.w);
        uint32_t* pv = Vs + r*TS_LD + c4*4;
        pv[0] = f2tf(vv.x); pv[1] = f2tf(vv.y); pv[2] = f2tf(vv.z); pv[3] = f2tf(vv.w);
    }
    __syncthreads();

    int warp = tid >> 5, lane = tid & 31;
    int g = lane >> 2, q = lane & 3;
    int rbase = warp * 16;         // query rows rbase..rbase+15
    int i = warp >> 2;             // slice
    int r0 = rbase + g, r1 = r0 + 8;

    // S frags (16 x 192), bias-initialized
    float4 c[24];
    {
        const float* bb = g_bias + ((size_t)((i*H_ + h)*INTV + (rbase & 63)))*KN;
#pragma unroll
        for (int kt = 0; kt < 24; ++kt) {
            int col = kt*8 + 2*q;
            float2 b0 = *(const float2*)(bb + (size_t)(g)*KN + col);
            float2 b1 = *(const float2*)(bb + (size_t)(g+8)*KN + col);
            c[kt] = make_float4(b0.x, b0.y, b1.x, b1.y);
        }
    }

    // S = scale*Q K^T + bias (keys mapped around excluded slice)
#pragma unroll
    for (int k0 = 0; k0 < 32; k0 += 8) {
        uint32_t a0 = Qs[r0*TS_LD + k0 + q];
        uint32_t a1 = Qs[r1*TS_LD + k0 + q];
        uint32_t a2 = Qs[r0*TS_LD + k0 + q + 4];
        uint32_t a3 = Qs[r1*TS_LD + k0 + q + 4];
#pragma unroll
        for (int kt = 0; kt < 24; ++kt) {
            int off = (kt*8 >= i*INTV) ? INTV : 0;
            int kg = kt*8 + g + off;
            uint32_t b0 = Ks[kg*TS_LD + k0 + q];
            uint32_t b1 = Ks[kg*TS_LD + k0 + q + 4];
            mma_tf32(c[kt], a0, a1, a2, a3, b0, b1);
        }
    }

    // in-warp softmax (rows r0, r1 span quad q=0..3 only)
    float mx0 = -1e30f, mx1 = -1e30f;
#pragma unroll
    for (int kt = 0; kt < 24; ++kt) {
        mx0 = fmaxf(mx0, fmaxf(c[kt].x, c[kt].y));
        mx1 = fmaxf(mx1, fmaxf(c[kt].z, c[kt].w));
    }
    mx0 = fmaxf(mx0, __shfl_xor_sync(0xffffffffu, mx0, 1));
    mx0 = fmaxf(mx0, __shfl_xor_sync(0xffffffffu, mx0, 2));
    mx1 = fmaxf(mx1, __shfl_xor_sync(0xffffffffu, mx1, 1));
    mx1 = fmaxf(mx1, __shfl_xor_sync(0xffffffffu, mx1, 2));

    float s0 = 0.f, s1 = 0.f;
#pragma unroll
    for (int kt = 0; kt < 24; ++kt) {
        c[kt].x = __expf(c[kt].x - mx0);
        c[kt].y = __expf(c[kt].y - mx0);
        c[kt].z = __expf(c[kt].z - mx1);
        c[kt].w = __expf(c[kt].w - mx1);
        s0 += c[kt].x + c[kt].y;
        s1 += c[kt].z + c[kt].w;
    }
    s0 += __shfl_xor_sync(0xffffffffu, s0, 1);
    s0 += __shfl_xor_sync(0xffffffffu, s0, 2);
    s1 += __shfl_xor_sync(0xffffffffu, s1, 1);
    s1 += __shfl_xor_sync(0xffffffffu, s1, 2);
    float inv0 = 1.f / s0;
    float inv1 = 1.f / s1;

    // PV: O(16x32) over 192 keys
    float4 o[4];
#pragma unroll
    for (int nj = 0; nj < 4; ++nj) o[nj] = make_float4(0.f,0.f,0.f,0.f);

    int srcA = (lane & ~3) | (q >> 1);
    int srcB = srcA + 2;
#pragma unroll
    for (int kt = 0; kt < 24; ++kt) {
        float t0 = __shfl_sync(0xffffffffu, c[kt].x, srcA);
        float t1 = __shfl_sync(0xffffffffu, c[kt].y, srcA);
        float t2 = __shfl_sync(0xffffffffu, c[kt].z, srcA);
        float t3 = __shfl_sync(0xffffffffu, c[kt].w, srcA);
        float t4 = __shfl_sync(0xffffffffu, c[kt].x, srcB);
        float t5 = __shfl_sync(0xffffffffu, c[kt].y, srcB);
        float t6 = __shfl_sync(0xffffffffu, c[kt].z, srcB);
        float t7 = __shfl_sync(0xffffffffu, c[kt].w, srcB);
        uint32_t a0 = f2tf((q & 1) ? t1 : t0);
        uint32_t a1 = f2tf((q & 1) ? t3 : t2);
        uint32_t a2 = f2tf((q & 1) ? t5 : t4);
        uint32_t a3 = f2tf((q & 1) ? t7 : t6);
        int off = (kt*8 >= i*INTV) ? INTV : 0;
        int kg0 = kt*8 + q + off;
#pragma unroll
        for (int nj = 0; nj < 4; ++nj) {
            uint32_t b0 = Vs[kg0*TS_LD     + nj*8 + g];
            uint32_t b1 = Vs[(kg0+4)*TS_LD + nj*8 + g];
            mma_tf32(o[nj], a0, a1, a2, a3, b0, b1);
        }
    }

    // normalize + write (warp-exclusive rows)
#pragma unroll
    for (int nj = 0; nj < 4; ++nj) {
        int cb = h*DH + nj*8 + 2*q;
        float2 v0 = make_float2(o[nj].x * inv0, o[nj].y * inv0);
        float2 v1 = make_float2(o[nj].z * inv1, o[nj].w * inv1);
        *(float2*)&g_att[((size_t)b*N_ + r0)*C_ + cb] = v0;
        *(float2*)&g_att[((size_t)b*N_ + r1)*C_ + cb] = v1;
    }
}

// ---------------------------------------------------------------------------
// Launch
// ---------------------------------------------------------------------------
extern "C" void kernel_launch(void* const* d_in, const int* in_sizes, int n_in,
                              void* d_out, int out_size) {
    const float* x      = (const float*)d_in[0];
    const float* q_w    = (const float*)d_in[1];
    const float* kv_w   = (const float*)d_in[2];
    const float* proj_w = (const float*)d_in[3];
    const float* proj_b = (const float*)d_in[4];
    const float* rpb    = (const float*)d_in[5];
    const int*   rel    = (const int*)d_in[6];
    float* out = (float*)d_out;

    const int qkv_smem  = (256*QA_LD + 128*QB_LD) * 4;   // 169,984 B
    const int proj_smem = (256*QA_LD + 128*PB_LD) * 4;   // 202,752 B
    const int attn_smem = (3*256*TS_LD) * 4;             // 110,592 B
    cudaFuncSetAttribute(qkv_gemm_tc,  cudaFuncAttributeMaxDynamicSharedMemorySize, qkv_smem);
    cudaFuncSetAttribute(proj_gemm_tc, cudaFuncAttributeMaxDynamicSharedMemorySize, proj_smem);
    cudaFuncSetAttribute(attn_tc,      cudaFuncAttributeMaxDynamicSharedMemorySize, attn_smem);

    bias_kernel<<<(T_*H_*INTV*KN + 255)/256, 256>>>(rpb, rel);
    qkv_gemm_tc<<<(B_*N_)/256, 512, qkv_smem>>>(x, q_w, kv_w);
    attn_tc<<<B_*H_, 512, attn_smem>>>();
    proj_gemm_tc<<<(B_*N_)/256, 512, proj_smem>>>(proj_w, proj_b, out);
}

// round 4
// speedup vs baseline: 3.5007x; 1.0243x over previous
#include <cuda_runtime.h>
#include <cstdint>

// Problem constants
#define B_   1024
#define N_   256
#define C_   128
#define H_   4
#define DH   32
#define T_   4
#define INTV 64
#define KN   192   // keys per slice = N - INTV

// Scratch (device globals; no dynamic allocation allowed)
__device__ float g_q[(size_t)B_*H_*N_*DH];       // [b][h][n][d]
__device__ float g_k[(size_t)B_*H_*N_*DH];
__device__ float g_v[(size_t)B_*H_*N_*DH];
__device__ float g_att[(size_t)B_*N_*C_];        // attention output, [b*n][c]
__device__ float g_bias[T_*H_*INTV*KN];          // [i][h][q][kk]

// ---------------------------------------------------------------------------
// helpers
// ---------------------------------------------------------------------------
__device__ __forceinline__ uint32_t f2tf(float f) {
    uint32_t u;
    asm("cvt.rna.tf32.f32 %0, %1;" : "=r"(u) : "f"(f));
    return u;
}

__device__ __forceinline__ void mma_tf32(float4& d,
                                         uint32_t a0, uint32_t a1, uint32_t a2, uint32_t a3,
                                         uint32_t b0, uint32_t b1) {
    asm volatile(
        "mma.sync.aligned.m16n8k8.row.col.f32.tf32.tf32.f32 "
        "{%0,%1,%2,%3}, {%4,%5,%6,%7}, {%8,%9}, {%0,%1,%2,%3};"
        : "+f"(d.x), "+f"(d.y), "+f"(d.z), "+f"(d.w)
        : "r"(a0), "r"(a1), "r"(a2), "r"(a3), "r"(b0), "r"(b1));
}

// ---------------------------------------------------------------------------
// Bias precompute
// ---------------------------------------------------------------------------
__global__ void bias_kernel(const float* __restrict__ rpb,
                            const int* __restrict__ rel) {
    int idx = blockIdx.x * 256 + threadIdx.x;
    if (idx >= T_*H_*INTV*KN) return;
    int kk = idx % KN;
    int q  = (idx / KN) % INTV;
    int h  = (idx / (KN*INTV)) % H_;
    int i  =  idx / (KN*INTV*H_);
    int qg = i*INTV + q;
    int kg = (kk < i*INTV) ? kk : kk + INTV;
    g_bias[idx] = rpb[rel[qg*N_ + kg]*H_ + h];
}

// ---------------------------------------------------------------------------
// QKV GEMM: block = 256 M-rows, A resident (read-once), 6 N-chunks of 64,
// double-buffered B with register prefetch. 512 threads, 16 warps 4(m)x4(n).
// ---------------------------------------------------------------------------
#define QA_LD 132
#define QB_LD 68

__device__ __forceinline__ void store_qkv(int m, int cg, float2 v) {
    int b = m >> 8, n = m & 255;
    if (cg < 128) {
        int h = cg >> 5, d = cg & 31;
        *(float2*)&g_q[(((size_t)b*H_ + h)*N_ + n)*DH + d] = v;
    } else if (cg < 256) {
        int cc = cg - 128; int h = cc >> 5, d = cc & 31;
        *(float2*)&g_k[(((size_t)b*H_ + h)*N_ + n)*DH + d] = v;
    } else {
        int cc = cg - 256; int h = cc >> 5, d = cc & 31;
        *(float2*)&g_v[(((size_t)b*H_ + h)*N_ + n)*DH + d] = v;
    }
}

__global__ __launch_bounds__(512) void qkv_gemm_tc(const float* __restrict__ x,
                                                   const float* __restrict__ q_w,
                                                   const float* __restrict__ kv_w) {
    extern __shared__ uint32_t sm[];
    uint32_t* As = sm;                    // [256][QA_LD]
    uint32_t* Bs0 = sm + 256*QA_LD;       // [128][QB_LD] x2 buffers
    uint32_t* Bs1 = Bs0 + 128*QB_LD;

    int tid   = threadIdx.x;
    int mBase = blockIdx.x * 256;

#pragma unroll
    for (int it = 0; it < 16; ++it) {     // A: 256x128
        int idx = tid + it*512;
        int r = idx >> 5, c4 = idx & 31;
        float4 v = *(const float4*)(x + (size_t)(mBase + r)*128 + c4*4);
        uint32_t* p = As + r*QA_LD + c4*4;
        p[0] = f2tf(v.x); p[1] = f2tf(v.y); p[2] = f2tf(v.z); p[3] = f2tf(v.w);
    }
    // B chunk 0 -> Bs0
    {
        int r = (tid + 0*512) >> 4;  // pattern below
#pragma unroll
        for (int it = 0; it < 4; ++it) {
            int idx = tid + it*512;
            int rr = idx >> 4, c4 = idx & 15;
            float4 v = *(const float4*)(q_w + (size_t)rr*128 + c4*4);
            uint32_t* p = Bs0 + rr*QB_LD + c4*4;
            p[0] = f2tf(v.x); p[1] = f2tf(v.y); p[2] = f2tf(v.z); p[3] = f2tf(v.w);
        }
        (void)r;
    }
    __syncthreads();

    int warp = tid >> 5, lane = tid & 31;
    int g = lane >> 2, q = lane & 3;
    int wm = (warp & 3) * 64;
    int wn = (warp >> 2) * 16;

#pragma unroll
    for (int c = 0; c < 6; ++c) {
        uint32_t* Bcur = (c & 1) ? Bs1 : Bs0;
        uint32_t* Bnxt = (c & 1) ? Bs0 : Bs1;

        // prefetch next chunk to registers (global latency hidden by mma)
        float4 pre[4];
        if (c < 5) {
            int cn = c + 1;
            const float* Bp; int bld, bcol;
            if (cn < 2) { Bp = q_w;  bld = 128; bcol = cn*64; }
            else        { Bp = kv_w; bld = 256; bcol = (cn-2)*64; }
#pragma unroll
            for (int it = 0; it < 4; ++it) {
                int idx = tid + it*512;
                int rr = idx >> 4, c4 = idx & 15;
                pre[it] = *(const float4*)(Bp + (size_t)rr*bld + bcol + c4*4);
            }
        }

        float4 acc[4][2];
#pragma unroll
        for (int mi = 0; mi < 4; ++mi)
#pragma unroll
            for (int nj = 0; nj < 2; ++nj) acc[mi][nj] = make_float4(0.f,0.f,0.f,0.f);

#pragma unroll
        for (int k0 = 0; k0 < 128; k0 += 8) {
            uint32_t a[4][4];
#pragma unroll
            for (int mi = 0; mi < 4; ++mi) {
                int r = wm + mi*16 + g;
                a[mi][0] = As[r*QA_LD + k0 + q];
                a[mi][1] = As[(r+8)*QA_LD + k0 + q];
                a[mi][2] = As[r*QA_LD + k0 + q + 4];
                a[mi][3] = As[(r+8)*QA_LD + k0 + q + 4];
            }
#pragma unroll
            for (int nj = 0; nj < 2; ++nj) {
                uint32_t b0 = Bcur[(k0+q)*QB_LD   + wn + nj*8 + g];
                uint32_t b1 = Bcur[(k0+q+4)*QB_LD + wn + nj*8 + g];
#pragma unroll
                for (int mi = 0; mi < 4; ++mi)
                    mma_tf32(acc[mi][nj], a[mi][0], a[mi][1], a[mi][2], a[mi][3], b0, b1);
            }
        }

        // stage prefetched B into the other buffer
        if (c < 5) {
#pragma unroll
            for (int it = 0; it < 4; ++it) {
                int idx = tid + it*512;
                int rr = idx >> 4, c4 = idx & 15;
                uint32_t* p = Bnxt + rr*QB_LD + c4*4;
                p[0] = f2tf(pre[it].x); p[1] = f2tf(pre[it].y);
                p[2] = f2tf(pre[it].z); p[3] = f2tf(pre[it].w);
            }
        }

#pragma unroll
        for (int mi = 0; mi < 4; ++mi)
#pragma unroll
            for (int nj = 0; nj < 2; ++nj) {
                int r  = mBase + wm + mi*16 + g;
                int cg = c*64 + wn + nj*8 + 2*q;
                store_qkv(r,     cg, make_float2(acc[mi][nj].x, acc[mi][nj].y));
                store_qkv(r + 8, cg, make_float2(acc[mi][nj].z, acc[mi][nj].w));
            }
        __syncthreads();
    }
}

// ---------------------------------------------------------------------------
// Projection GEMM: block = 256 x 128 (single N pass, A read-once).
// ---------------------------------------------------------------------------
#define PB_LD 132

__global__ __launch_bounds__(512) void proj_gemm_tc(const float* __restrict__ pw,
                                                    const float* __restrict__ pb,
                                                    float* __restrict__ out) {
    extern __shared__ uint32_t sm[];
    uint32_t* As = sm;                   // [256][QA_LD]
    uint32_t* Bs = sm + 256*QA_LD;       // [128][PB_LD]

    int tid   = threadIdx.x;
    int mBase = blockIdx.x * 256;

#pragma unroll
    for (int it = 0; it < 16; ++it) {
        int idx = tid + it*512;
        int r = idx >> 5, c4 = idx & 31;
        float4 v = *(const float4*)(g_att + (size_t)(mBase + r)*128 + c4*4);
        uint32_t* p = As + r*QA_LD + c4*4;
        p[0] = f2tf(v.x); p[1] = f2tf(v.y); p[2] = f2tf(v.z); p[3] = f2tf(v.w);
    }
#pragma unroll
    for (int it = 0; it < 8; ++it) {
        int idx = tid + it*512;
        int r = idx >> 5, c4 = idx & 31;
        float4 v = *(const float4*)(pw + (size_t)r*128 + c4*4);
        uint32_t* p = Bs + r*PB_LD + c4*4;
        p[0] = f2tf(v.x); p[1] = f2tf(v.y); p[2] = f2tf(v.z); p[3] = f2tf(v.w);
    }
    __syncthreads();

    int warp = tid >> 5, lane = tid & 31;
    int g = lane >> 2, q = lane & 3;
    int wm = (warp & 3) * 64;
    int wn = (warp >> 2) * 32;

    float4 acc[4][4];
#pragma unroll
    for (int mi = 0; mi < 4; ++mi)
#pragma unroll
        for (int nj = 0; nj < 4; ++nj) acc[mi][nj] = make_float4(0.f,0.f,0.f,0.f);

#pragma unroll
    for (int k0 = 0; k0 < 128; k0 += 8) {
        uint32_t a[4][4];
#pragma unroll
        for (int mi = 0; mi < 4; ++mi) {
            int r = wm + mi*16 + g;
            a[mi][0] = As[r*QA_LD + k0 + q];
            a[mi][1] = As[(r+8)*QA_LD + k0 + q];
            a[mi][2] = As[r*QA_LD + k0 + q + 4];
            a[mi][3] = As[(r+8)*QA_LD + k0 + q + 4];
        }
#pragma unroll
        for (int nj = 0; nj < 4; ++nj) {
            uint32_t b0 = Bs[(k0+q)*PB_LD   + wn + nj*8 + g];
            uint32_t b1 = Bs[(k0+q+4)*PB_LD + wn + nj*8 + g];
#pragma unroll
            for (int mi = 0; mi < 4; ++mi)
                mma_tf32(acc[mi][nj], a[mi][0], a[mi][1], a[mi][2], a[mi][3], b0, b1);
        }
    }

#pragma unroll
    for (int nj = 0; nj < 4; ++nj) {
        int cg = wn + nj*8 + 2*q;
        float2 bias = *(const float2*)(pb + cg);
#pragma unroll
        for (int mi = 0; mi < 4; ++mi) {
            int r = mBase + wm + mi*16 + g;
            float2 v0 = make_float2(acc[mi][nj].x + bias.x, acc[mi][nj].y + bias.y);
            float2 v1 = make_float2(acc[mi][nj].z + bias.x, acc[mi][nj].w + bias.y);
            *(float2*)&out[(size_t)r*C_ + cg]     = v0;
            *(float2*)&out[(size_t)(r+8)*C_ + cg] = v1;
        }
    }
}

// ---------------------------------------------------------------------------
// Attention: block per (b, h), 512 threads (16 warps). Q/K/V (256x32 each)
// loaded once. Warp w owns query rows w*16..w*16+15 (slice i = w/4), all
// 192 keys processed in TWO 96-key chunks with online softmax (12 live
// S-frags -> no register spills at the 128-reg cap). Shuffle-transform feeds
// PV mma; O rescaled between chunks.
// ---------------------------------------------------------------------------
#define TS_LD 36

__global__ __launch_bounds__(512) void attn_tc() {
    extern __shared__ uint32_t sm[];
    uint32_t* Qs = sm;                   // [256][TS_LD]
    uint32_t* Ks = sm + 256*TS_LD;
    uint32_t* Vs = sm + 512*TS_LD;

    int tid = threadIdx.x;
    int bid = blockIdx.x;
    int h = bid & 3, b = bid >> 2;
    size_t base = ((size_t)b*H_ + h) * N_ * DH;

    const float scale = 0.17677669529663687f;  // 32^-0.5

#pragma unroll
    for (int it = 0; it < 4; ++it) {     // Q,K,V: 256x32 each
        int idx = tid + it*512;
        int r = idx >> 3, c4 = idx & 7;
        float4 qv = *(const float4*)(g_q + base + (size_t)r*DH + c4*4);
        float4 kv = *(const float4*)(g_k + base + (size_t)r*DH + c4*4);
        float4 vv = *(const float4*)(g_v + base + (size_t)r*DH + c4*4);
        uint32_t* pq = Qs + r*TS_LD + c4*4;
        pq[0] = f2tf(qv.x*scale); pq[1] = f2tf(qv.y*scale);
        pq[2] = f2tf(qv.z*scale); pq[3] = f2tf(qv.w*scale);
        uint32_t* pk = Ks + r*TS_LD + c4*4;
        pk[0] = f2tf(kv.x); pk[1] = f2tf(kv.y); pk[2] = f2tf(kv.z); pk[3] = f2tf(kv.w);
        uint32_t* pv = Vs + r*TS_LD + c4*4;
        pv[0] = f2tf(vv.x); pv[1] = f2tf(vv.y); pv[2] = f2tf(vv.z); pv[3] = f2tf(vv.w);
    }
    __syncthreads();

    int warp = tid >> 5, lane = tid & 31;
    int g = lane >> 2, q = lane & 3;
    int rbase = warp * 16;         // query rows rbase..rbase+15
    int i = warp >> 2;             // slice
    int r0 = rbase + g, r1 = r0 + 8;

    const float* bb = g_bias + ((size_t)((i*H_ + h)*INTV + (rbase & 63)))*KN;
    int srcA = (lane & ~3) | (q >> 1);
    int srcB = srcA + 2;

    float m0r = -1e30f, m1r = -1e30f;
    float s0r = 0.f, s1r = 0.f;
    float4 o[4];
#pragma unroll
    for (int nj = 0; nj < 4; ++nj) o[nj] = make_float4(0.f,0.f,0.f,0.f);

#pragma unroll
    for (int ch = 0; ch < 2; ++ch) {
        int cbase = ch * 96;

        // S frags (16 x 96), bias-initialized
        float4 c[12];
#pragma unroll
        for (int kt = 0; kt < 12; ++kt) {
            int col = cbase + kt*8 + 2*q;
            float2 b0 = *(const float2*)(bb + (size_t)(g)*KN + col);
            float2 b1 = *(const float2*)(bb + (size_t)(g+8)*KN + col);
            c[kt] = make_float4(b0.x, b0.y, b1.x, b1.y);
        }

        // S = scale*Q K^T + bias (keys mapped around excluded slice)
#pragma unroll
        for (int k0 = 0; k0 < 32; k0 += 8) {
            uint32_t a0 = Qs[r0*TS_LD + k0 + q];
            uint32_t a1 = Qs[r1*TS_LD + k0 + q];
            uint32_t a2 = Qs[r0*TS_LD + k0 + q + 4];
            uint32_t a3 = Qs[r1*TS_LD + k0 + q + 4];
#pragma unroll
            for (int kt = 0; kt < 12; ++kt) {
                int col = cbase + kt*8;
                int off = (col >= i*INTV) ? INTV : 0;
                int kg = col + g + off;
                uint32_t b0 = Ks[kg*TS_LD + k0 + q];
                uint32_t b1 = Ks[kg*TS_LD + k0 + q + 4];
                mma_tf32(c[kt], a0, a1, a2, a3, b0, b1);
            }
        }

        // chunk max
        float mx0 = -1e30f, mx1 = -1e30f;
#pragma unroll
        for (int kt = 0; kt < 12; ++kt) {
            mx0 = fmaxf(mx0, fmaxf(c[kt].x, c[kt].y));
            mx1 = fmaxf(mx1, fmaxf(c[kt].z, c[kt].w));
        }
        mx0 = fmaxf(mx0, __shfl_xor_sync(0xffffffffu, mx0, 1));
        mx0 = fmaxf(mx0, __shfl_xor_sync(0xffffffffu, mx0, 2));
        mx1 = fmaxf(mx1, __shfl_xor_sync(0xffffffffu, mx1, 1));
        mx1 = fmaxf(mx1, __shfl_xor_sync(0xffffffffu, mx1, 2));

        float mn0 = fmaxf(m0r, mx0), mn1 = fmaxf(m1r, mx1);
        float sc0 = __expf(m0r - mn0), sc1 = __expf(m1r - mn1);
        m0r = mn0; m1r = mn1;

        // exp + chunk sum
        float cs0 = 0.f, cs1 = 0.f;
#pragma unroll
        for (int kt = 0; kt < 12; ++kt) {
            c[kt].x = __expf(c[kt].x - mn0);
            c[kt].y = __expf(c[kt].y - mn0);
            c[kt].z = __expf(c[kt].z - mn1);
            c[kt].w = __expf(c[kt].w - mn1);
            cs0 += c[kt].x + c[kt].y;
            cs1 += c[kt].z + c[kt].w;
        }
        cs0 += __shfl_xor_sync(0xffffffffu, cs0, 1);
        cs0 += __shfl_xor_sync(0xffffffffu, cs0, 2);
        cs1 += __shfl_xor_sync(0xffffffffu, cs1, 1);
        cs1 += __shfl_xor_sync(0xffffffffu, cs1, 2);
        s0r = s0r*sc0 + cs0;
        s1r = s1r*sc1 + cs1;

        // rescale O
#pragma unroll
        for (int nj = 0; nj < 4; ++nj) {
            o[nj].x *= sc0; o[nj].y *= sc0;
            o[nj].z *= sc1; o[nj].w *= sc1;
        }

        // PV accumulate over this chunk's 96 keys
#pragma unroll
        for (int kt = 0; kt < 12; ++kt) {
            float t0 = __shfl_sync(0xffffffffu, c[kt].x, srcA);
            float t1 = __shfl_sync(0xffffffffu, c[kt].y, srcA);
            float t2 = __shfl_sync(0xffffffffu, c[kt].z, srcA);
            float t3 = __shfl_sync(0xffffffffu, c[kt].w, srcA);
            float t4 = __shfl_sync(0xffffffffu, c[kt].x, srcB);
            float t5 = __shfl_sync(0xffffffffu, c[kt].y, srcB);
            float t6 = __shfl_sync(0xffffffffu, c[kt].z, srcB);
            float t7 = __shfl_sync(0xffffffffu, c[kt].w, srcB);
            uint32_t a0 = f2tf((q & 1) ? t1 : t0);
            uint32_t a1 = f2tf((q & 1) ? t3 : t2);
            uint32_t a2 = f2tf((q & 1) ? t5 : t4);
            uint32_t a3 = f2tf((q & 1) ? t7 : t6);
            int col = cbase + kt*8;
            int off = (col >= i*INTV) ? INTV : 0;
            int kg0 = col + q + off;
#pragma unroll
            for (int nj = 0; nj < 4; ++nj) {
                uint32_t b0 = Vs[kg0*TS_LD     + nj*8 + g];
                uint32_t b1 = Vs[(kg0+4)*TS_LD + nj*8 + g];
                mma_tf32(o[nj], a0, a1, a2, a3, b0, b1);
            }
        }
    }

    float inv0 = 1.f / s0r;
    float inv1 = 1.f / s1r;

    // normalize + write (warp-exclusive rows)
#pragma unroll
    for (int nj = 0; nj < 4; ++nj) {
        int cb = h*DH + nj*8 + 2*q;
        float2 v0 = make_float2(o[nj].x * inv0, o[nj].y * inv0);
        float2 v1 = make_float2(o[nj].z * inv1, o[nj].w * inv1);
        *(float2*)&g_att[((size_t)b*N_ + r0)*C_ + cb] = v0;
        *(float2*)&g_att[((size_t)b*N_ + r1)*C_ + cb] = v1;
    }
}

// ---------------------------------------------------------------------------
// Launch
// ---------------------------------------------------------------------------
extern "C" void kernel_launch(void* const* d_in, const int* in_sizes, int n_in,
                              void* d_out, int out_size) {
    const float* x      = (const float*)d_in[0];
    const float* q_w    = (const float*)d_in[1];
    const float* kv_w   = (const float*)d_in[2];
    const float* proj_w = (const float*)d_in[3];
    const float* proj_b = (const float*)d_in[4];
    const float* rpb    = (const float*)d_in[5];
    const int*   rel    = (const int*)d_in[6];
    float* out = (float*)d_out;

    const int qkv_smem  = (256*QA_LD + 2*128*QB_LD) * 4;  // 204,800 B
    const int proj_smem = (256*QA_LD + 128*PB_LD) * 4;    // 202,752 B
    const int attn_smem = (3*256*TS_LD) * 4;              // 110,592 B
    cudaFuncSetAttribute(qkv_gemm_tc,  cudaFuncAttributeMaxDynamicSharedMemorySize, qkv_smem);
    cudaFuncSetAttribute(proj_gemm_tc, cudaFuncAttributeMaxDynamicSharedMemorySize, proj_smem);
    cudaFuncSetAttribute(attn_tc,      cudaFuncAttributeMaxDynamicSharedMemorySize, attn_smem);

    bias_kernel<<<(T_*H_*INTV*KN + 255)/256, 256>>>(rpb, rel);
    qkv_gemm_tc<<<(B_*N_)/256, 512, qkv_smem>>>(x, q_w, kv_w);
    attn_tc<<<B_*H_, 512, attn_smem>>>();
    proj_gemm_tc<<<(B_*N_)/256, 512, proj_smem>>>(proj_w, proj_b, out);
}